// round 1
// baseline (speedup 1.0000x reference)
#include <cuda_runtime.h>
#include <cstdint>

#define T_ 128
#define V_ 5023
#define K_ 16
#define NTV (T_ * V_)

// 0 = uint8 (numpy bool), 1 = int32, 2 = float32
__device__ int g_mask_mode;

__global__ void detect_mask_kernel(const unsigned int* __restrict__ w) {
    __shared__ int flags[3];
    if (threadIdx.x < 3) flags[threadIdx.x] = 0;
    __syncthreads();
    // Scan first 512 words (2048 bytes; safe: mask buffer >= V_*K_ >= 80368 bytes/elems)
    for (int i = threadIdx.x; i < 512; i += blockDim.x) {
        unsigned int x = w[i];
        if (x == 0u) continue;
        if (x == 1u) atomicOr(&flags[0], 1);
        else if (x == 0x3F800000u) atomicOr(&flags[1], 1);
        else atomicOr(&flags[2], 1);
    }
    __syncthreads();
    if (threadIdx.x == 0) {
        // packed-byte patterns (e.g. 0x01010101) => uint8 bools
        g_mask_mode = flags[2] ? 0 : (flags[1] ? 2 : 1);
    }
}

__global__ void __launch_bounds__(256)
se3_kernel(const float* __restrict__ can, const float* __restrict__ def,
           const int* __restrict__ nbr, const void* __restrict__ maskp,
           float* __restrict__ out) {
    int idx = blockIdx.x * 256 + threadIdx.x;
    if (idx >= NTV) return;
    int t = idx / V_;
    int v = idx - t * V_;

    const float* canT = can + (size_t)t * (V_ * 3);
    const float* defT = def + (size_t)t * (V_ * 3);

    // ---- load mask row (dtype-robust) ----
    float m[K_];
    int mode = g_mask_mode;
    if (mode == 0) {
        uint4 mw = *(const uint4*)((const unsigned char*)maskp + (size_t)v * K_);
        unsigned int ws[4] = {mw.x, mw.y, mw.z, mw.w};
#pragma unroll
        for (int i = 0; i < K_; i++)
            m[i] = ((ws[i >> 2] >> ((i & 3) * 8)) & 0xFF) ? 1.0f : 0.0f;
    } else if (mode == 1) {
        const int4* mi = (const int4*)((const int*)maskp + (size_t)v * K_);
#pragma unroll
        for (int c = 0; c < 4; c++) {
            int4 x = mi[c];
            m[c * 4 + 0] = x.x ? 1.0f : 0.0f;
            m[c * 4 + 1] = x.y ? 1.0f : 0.0f;
            m[c * 4 + 2] = x.z ? 1.0f : 0.0f;
            m[c * 4 + 3] = x.w ? 1.0f : 0.0f;
        }
    } else {
        const float4* mf = (const float4*)((const float*)maskp + (size_t)v * K_);
#pragma unroll
        for (int c = 0; c < 4; c++) {
            float4 x = mf[c];
            m[c * 4 + 0] = x.x; m[c * 4 + 1] = x.y;
            m[c * 4 + 2] = x.z; m[c * 4 + 3] = x.w;
        }
    }

    // ---- load neighbor indices ----
    int nb[K_];
    const int4* ni = (const int4*)(nbr + (size_t)v * K_);
#pragma unroll
    for (int c = 0; c < 4; c++) {
        int4 x = ni[c];
        nb[c * 4 + 0] = x.x; nb[c * 4 + 1] = x.y;
        nb[c * 4 + 2] = x.z; nb[c * 4 + 3] = x.w;
    }

    float cx = canT[v * 3 + 0], cy = canT[v * 3 + 1], cz = canT[v * 3 + 2];
    float dx = defT[v * 3 + 0], dy = defT[v * 3 + 1], dz = defT[v * 3 + 2];

    // ---- cross-covariance A = sum_k q_c p_c^T  (A[i][j] = sum q_i * p_j) ----
    float A00 = 0, A01 = 0, A02 = 0;
    float A10 = 0, A11 = 0, A12 = 0;
    float A20 = 0, A21 = 0, A22 = 0;
#pragma unroll
    for (int k = 0; k < K_; k++) {
        int j3 = nb[k] * 3;
        float mk = m[k];
        float px = fmaf(canT[j3 + 0], mk, -cx);
        float py = fmaf(canT[j3 + 1], mk, -cy);
        float pz = fmaf(canT[j3 + 2], mk, -cz);
        float qx = fmaf(defT[j3 + 0], mk, -dx);
        float qy = fmaf(defT[j3 + 1], mk, -dy);
        float qz = fmaf(defT[j3 + 2], mk, -dz);
        A00 = fmaf(qx, px, A00); A01 = fmaf(qx, py, A01); A02 = fmaf(qx, pz, A02);
        A10 = fmaf(qy, px, A10); A11 = fmaf(qy, py, A11); A12 = fmaf(qy, pz, A12);
        A20 = fmaf(qz, px, A20); A21 = fmaf(qz, py, A21); A22 = fmaf(qz, pz, A22);
    }

    // ---- Davenport K matrix: max eigenvector = optimal quaternion (w,x,y,z) ----
    float Km[4][4];
    Km[0][0] = A00 + A11 + A22;
    Km[1][1] = A00 - A11 - A22;
    Km[2][2] = -A00 + A11 - A22;
    Km[3][3] = -A00 - A11 + A22;
    Km[0][1] = Km[1][0] = A21 - A12;
    Km[0][2] = Km[2][0] = A02 - A20;
    Km[0][3] = Km[3][0] = A10 - A01;
    Km[1][2] = Km[2][1] = A01 + A10;
    Km[1][3] = Km[3][1] = A02 + A20;
    Km[2][3] = Km[3][2] = A12 + A21;

    float Q[4][4] = {{1, 0, 0, 0}, {0, 1, 0, 0}, {0, 0, 1, 0}, {0, 0, 0, 1}};

    const int pidx[6] = {0, 0, 0, 1, 1, 2};
    const int qidx[6] = {1, 2, 3, 2, 3, 3};
#pragma unroll
    for (int sweep = 0; sweep < 5; sweep++) {
#pragma unroll
        for (int pr = 0; pr < 6; pr++) {
            const int p = pidx[pr], q = qidx[pr];
            float apq = Km[p][q];
            if (apq * apq > 1e-30f) {
                float theta = (Km[q][q] - Km[p][p]) * 0.5f / apq;
                float tt = copysignf(1.0f, theta) /
                           (fabsf(theta) + sqrtf(fmaf(theta, theta, 1.0f)));
                float c = rsqrtf(fmaf(tt, tt, 1.0f));
                float s = tt * c;
                // K <- G^T K G
#pragma unroll
                for (int i = 0; i < 4; i++) {
                    float a = Km[p][i], b = Km[q][i];
                    Km[p][i] = c * a - s * b;
                    Km[q][i] = s * a + c * b;
                }
#pragma unroll
                for (int i = 0; i < 4; i++) {
                    float a = Km[i][p], b = Km[i][q];
                    Km[i][p] = c * a - s * b;
                    Km[i][q] = s * a + c * b;
                }
                // Q <- Q G (columns are eigenvectors)
#pragma unroll
                for (int i = 0; i < 4; i++) {
                    float a = Q[i][p], b = Q[i][q];
                    Q[i][p] = c * a - s * b;
                    Q[i][q] = s * a + c * b;
                }
            }
        }
    }

    // argmax eigenvalue (first on ties)
    int jm = 0;
    float bev = Km[0][0];
#pragma unroll
    for (int j = 1; j < 4; j++) {
        if (Km[j][j] > bev) { bev = Km[j][j]; jm = j; }
    }
    float qw = Q[0][jm], qx = Q[1][jm], qy = Q[2][jm], qz = Q[3][jm];

    // sign convention: largest-|component| (first on ties) made positive; unit norm
    float aw = fabsf(qw), ax = fabsf(qx), ay = fabsf(qy), az = fabsf(qz);
    float besta = aw, piv = qw;
    if (ax > besta) { besta = ax; piv = qx; }
    if (ay > besta) { besta = ay; piv = qy; }
    if (az > besta) { besta = az; piv = qz; }
    float invn = rsqrtf(fmaf(qw, qw, fmaf(qx, qx, fmaf(qy, qy, qz * qz))));
    if (piv < 0.0f) invn = -invn;

    // rotation: [T,V,4] at out[0..NTV*4)
    float4 rq = make_float4(qw * invn, qx * invn, qy * invn, qz * invn);
    ((float4*)out)[idx] = rq;

    // translation: [T,V,3] at out[NTV*4 ..)
    float* outt = out + (size_t)NTV * 4;
    outt[idx * 3 + 0] = dx - cx;
    outt[idx * 3 + 1] = dy - cy;
    outt[idx * 3 + 2] = dz - cz;
}

extern "C" void kernel_launch(void* const* d_in, const int* in_sizes, int n_in,
                              void* d_out, int out_size) {
    const float* can = (const float*)d_in[0];
    const float* def = (const float*)d_in[1];
    const int* nbr = (const int*)d_in[2];
    const void* mask = d_in[3];
    float* out = (float*)d_out;

    detect_mask_kernel<<<1, 128>>>((const unsigned int*)mask);
    int blocks = (NTV + 255) / 256;
    se3_kernel<<<blocks, 256>>>(can, def, nbr, mask, out);
}

// round 2
// speedup vs baseline: 2.2542x; 2.2542x over previous
#include <cuda_runtime.h>
#include <cstdint>

#define T_ 128
#define V_ 5023
#define K_ 16
#define NTV (T_ * V_)
#define THREADS 512

// 0 = uint8 (numpy bool), 1 = int32, 2 = float32
__device__ int g_mask_mode;

__global__ void detect_mask_kernel(const unsigned int* __restrict__ w) {
    __shared__ int flags[3];
    if (threadIdx.x < 3) flags[threadIdx.x] = 0;
    __syncthreads();
    for (int i = threadIdx.x; i < 512; i += blockDim.x) {
        unsigned int x = w[i];
        if (x == 0u) continue;
        if (x == 1u) atomicOr(&flags[0], 1);
        else if (x == 0x3F800000u) atomicOr(&flags[1], 1);
        else atomicOr(&flags[2], 1);
    }
    __syncthreads();
    if (threadIdx.x == 0) {
        g_mask_mode = flags[2] ? 0 : (flags[1] ? 2 : 1);
    }
}

extern __shared__ float4 s_buf[];  // [2 * V_] : can4 then def4

__global__ void __launch_bounds__(THREADS)
se3_frame_kernel(const float* __restrict__ can, const float* __restrict__ def,
                 const int* __restrict__ nbr, const void* __restrict__ maskp,
                 float* __restrict__ out) {
    const int t = blockIdx.x;
    const int tid = threadIdx.x;
    float4* can4 = s_buf;
    float4* def4 = s_buf + V_;
    const float* canT = can + (size_t)t * (V_ * 3);
    const float* defT = def + (size_t)t * (V_ * 3);

    // ---- stage this frame's positions into smem as float4 ----
    for (int v = tid; v < V_; v += THREADS) {
        int b = 3 * v;
        can4[v] = make_float4(canT[b], canT[b + 1], canT[b + 2], 0.0f);
        def4[v] = make_float4(defT[b], defT[b + 1], defT[b + 2], 0.0f);
    }
    __syncthreads();

    const int mode = g_mask_mode;
    float* outt = out + (size_t)NTV * 4;

    for (int v = tid; v < V_; v += THREADS) {
        // ---- mask row (dtype-robust) ----
        float m[K_];
        if (mode == 0) {
            uint4 mw = *(const uint4*)((const unsigned char*)maskp + (size_t)v * K_);
            unsigned int ws[4] = {mw.x, mw.y, mw.z, mw.w};
#pragma unroll
            for (int i = 0; i < K_; i++)
                m[i] = ((ws[i >> 2] >> ((i & 3) * 8)) & 0xFF) ? 1.0f : 0.0f;
        } else if (mode == 1) {
            const int4* mi = (const int4*)((const int*)maskp + (size_t)v * K_);
#pragma unroll
            for (int c = 0; c < 4; c++) {
                int4 x = mi[c];
                m[c * 4 + 0] = x.x ? 1.0f : 0.0f;
                m[c * 4 + 1] = x.y ? 1.0f : 0.0f;
                m[c * 4 + 2] = x.z ? 1.0f : 0.0f;
                m[c * 4 + 3] = x.w ? 1.0f : 0.0f;
            }
        } else {
            const float4* mf = (const float4*)((const float*)maskp + (size_t)v * K_);
#pragma unroll
            for (int c = 0; c < 4; c++) {
                float4 x = mf[c];
                m[c * 4 + 0] = x.x; m[c * 4 + 1] = x.y;
                m[c * 4 + 2] = x.z; m[c * 4 + 3] = x.w;
            }
        }

        // ---- neighbor indices ----
        int nb[K_];
        const int4* ni = (const int4*)(nbr + (size_t)v * K_);
#pragma unroll
        for (int c = 0; c < 4; c++) {
            int4 x = ni[c];
            nb[c * 4 + 0] = x.x; nb[c * 4 + 1] = x.y;
            nb[c * 4 + 2] = x.z; nb[c * 4 + 3] = x.w;
        }

        float4 cc = can4[v];
        float4 dd = def4[v];
        float cx = cc.x, cy = cc.y, cz = cc.z;
        float dx = dd.x, dy = dd.y, dz = dd.z;

        // ---- cross-covariance A[i][j] = sum_k q_i * p_j (gathers from smem) ----
        float A00 = 0, A01 = 0, A02 = 0;
        float A10 = 0, A11 = 0, A12 = 0;
        float A20 = 0, A21 = 0, A22 = 0;
#pragma unroll
        for (int k = 0; k < K_; k++) {
            int j = nb[k];
            float mk = m[k];
            float4 P = can4[j];
            float4 Q = def4[j];
            float px = fmaf(P.x, mk, -cx);
            float py = fmaf(P.y, mk, -cy);
            float pz = fmaf(P.z, mk, -cz);
            float qx = fmaf(Q.x, mk, -dx);
            float qy = fmaf(Q.y, mk, -dy);
            float qz = fmaf(Q.z, mk, -dz);
            A00 = fmaf(qx, px, A00); A01 = fmaf(qx, py, A01); A02 = fmaf(qx, pz, A02);
            A10 = fmaf(qy, px, A10); A11 = fmaf(qy, py, A11); A12 = fmaf(qy, pz, A12);
            A20 = fmaf(qz, px, A20); A21 = fmaf(qz, py, A21); A22 = fmaf(qz, pz, A22);
        }

        // ---- Davenport K matrix (symmetric, trace 0) ----
        float k00 = A00 + A11 + A22;
        float k11 = A00 - A11 - A22;
        float k22 = -A00 + A11 - A22;
        float k33 = -A00 - A11 + A22;
        float k01 = A21 - A12;
        float k02 = A02 - A20;
        float k03 = A10 - A01;
        float k12 = A01 + A10;
        float k13 = A02 + A20;
        float k23 = A12 + A21;

        // ---- characteristic quartic: f(x) = x^4 + c2 x^2 + c1 x + c0 ----
        float trAtA = A00 * A00 + A01 * A01 + A02 * A02 +
                      A10 * A10 + A11 * A11 + A12 * A12 +
                      A20 * A20 + A21 * A21 + A22 * A22;
        float c2 = -2.0f * trAtA;
        float detA = A00 * (A11 * A22 - A12 * A21)
                   - A01 * (A10 * A22 - A12 * A20)
                   + A02 * (A10 * A21 - A11 * A20);
        float c1 = -8.0f * detA;
        // c0 = det(K) by cofactor expansion along row 0
        float M0 = k11 * (k22 * k33 - k23 * k23)
                 - k12 * (k12 * k33 - k23 * k13)
                 + k13 * (k12 * k23 - k22 * k13);
        float M1 = k01 * (k22 * k33 - k23 * k23)
                 - k12 * (k02 * k33 - k23 * k03)
                 + k13 * (k02 * k23 - k22 * k03);
        float M2 = k01 * (k12 * k33 - k23 * k13)
                 - k11 * (k02 * k33 - k23 * k03)
                 + k13 * (k02 * k13 - k12 * k03);
        float M3 = k01 * (k12 * k23 - k22 * k13)
                 - k11 * (k02 * k23 - k22 * k03)
                 + k12 * (k02 * k13 - k12 * k03);
        float c0 = k00 * M0 - k01 * M1 + k02 * M2 - k03 * M3;

        // ---- Newton from upper bound lam0 = sqrt(3 * tr(A^T A)) >= lam_max ----
        float lam = 1.7320508f * sqrtf(trAtA);
        float fp = 1.0f;
#pragma unroll
        for (int it = 0; it < 9; it++) {
            float lam2 = lam * lam;
            float f = (lam2 + c2) * lam2 + fmaf(c1, lam, c0);
            fp = fmaf(4.0f * lam2 + 2.0f * c2, lam, c1);
            lam -= __fdividef(f, fp);
        }

        // ---- eigenvector via -adj(B), B = K - lam*I ----
        // M = B^3 + a3 B^2 + a2 B + a1 I, a3=4lam, a2=6lam^2+c2, a1=f'(lam)
        float b00 = k00 - lam, b11 = k11 - lam, b22 = k22 - lam, b33 = k33 - lam;
        float a3 = 4.0f * lam;
        float a2 = fmaf(6.0f * lam, lam, c2);
        float a1 = fp;

        // C = B^2 (symmetric)
        float C00 = b00 * b00 + k01 * k01 + k02 * k02 + k03 * k03;
        float C01 = b00 * k01 + k01 * b11 + k02 * k12 + k03 * k13;
        float C02 = b00 * k02 + k01 * k12 + k02 * b22 + k03 * k23;
        float C03 = b00 * k03 + k01 * k13 + k02 * k23 + k03 * b33;
        float C11 = k01 * k01 + b11 * b11 + k12 * k12 + k13 * k13;
        float C12 = k01 * k02 + b11 * k12 + k12 * b22 + k13 * k23;
        float C13 = k01 * k03 + b11 * k13 + k12 * k23 + k13 * b33;
        float C22 = k02 * k02 + k12 * k12 + b22 * b22 + k23 * k23;
        float C23 = k02 * k03 + k12 * k13 + b22 * k23 + k23 * b33;
        float C33 = k03 * k03 + k13 * k13 + k23 * k23 + b33 * b33;

        // P = B * C (= B^3, symmetric since B,C commute)
        float P00 = b00 * C00 + k01 * C01 + k02 * C02 + k03 * C03;
        float P01 = b00 * C01 + k01 * C11 + k02 * C12 + k03 * C13;
        float P02 = b00 * C02 + k01 * C12 + k02 * C22 + k03 * C23;
        float P03 = b00 * C03 + k01 * C13 + k02 * C23 + k03 * C33;
        float P11 = k01 * C01 + b11 * C11 + k12 * C12 + k13 * C13;
        float P12 = k01 * C02 + b11 * C12 + k12 * C22 + k13 * C23;
        float P13 = k01 * C03 + b11 * C13 + k12 * C23 + k13 * C33;
        float P22 = k02 * C02 + k12 * C12 + b22 * C22 + k23 * C23;
        float P23 = k02 * C03 + k12 * C13 + b22 * C23 + k23 * C33;
        float P33 = k03 * C03 + k13 * C13 + k23 * C23 + b33 * C33;

        float M00 = P00 + a3 * C00 + a2 * b00 + a1;
        float M01 = P01 + a3 * C01 + a2 * k01;
        float M02 = P02 + a3 * C02 + a2 * k02;
        float M03 = P03 + a3 * C03 + a2 * k03;
        float M11 = P11 + a3 * C11 + a2 * b11 + a1;
        float M12 = P12 + a3 * C12 + a2 * k12;
        float M13 = P13 + a3 * C13 + a2 * k13;
        float M22 = P22 + a3 * C22 + a2 * b22 + a1;
        float M23 = P23 + a3 * C23 + a2 * k23;
        float M33 = P33 + a3 * C33 + a2 * b33 + a1;

        // pick the column with the largest |diagonal| (best-conditioned)
        float qw = M00, qx = M01, qy = M02, qz = M03;
        float bd = fabsf(M00);
        if (fabsf(M11) > bd) { bd = fabsf(M11); qw = M01; qx = M11; qy = M12; qz = M13; }
        if (fabsf(M22) > bd) { bd = fabsf(M22); qw = M02; qx = M12; qy = M22; qz = M23; }
        if (fabsf(M33) > bd) { bd = fabsf(M33); qw = M03; qx = M13; qy = M23; qz = M33; }

        // sign convention: component with largest |value| (w,x,y,z order, first on ties) positive
        float aw = fabsf(qw), ax = fabsf(qx), ay = fabsf(qy), az = fabsf(qz);
        float besta = aw, piv = qw;
        if (ax > besta) { besta = ax; piv = qx; }
        if (ay > besta) { besta = ay; piv = qy; }
        if (az > besta) { besta = az; piv = qz; }
        float invn = rsqrtf(fmaf(qw, qw, fmaf(qx, qx, fmaf(qy, qy, qz * qz))));
        if (piv < 0.0f) invn = -invn;

        int idx = t * V_ + v;
        ((float4*)out)[idx] = make_float4(qw * invn, qx * invn, qy * invn, qz * invn);
        outt[idx * 3 + 0] = dx - cx;
        outt[idx * 3 + 1] = dy - cy;
        outt[idx * 3 + 2] = dz - cz;
    }
}

extern "C" void kernel_launch(void* const* d_in, const int* in_sizes, int n_in,
                              void* d_out, int out_size) {
    const float* can = (const float*)d_in[0];
    const float* def = (const float*)d_in[1];
    const int* nbr = (const int*)d_in[2];
    const void* mask = d_in[3];
    float* out = (float*)d_out;

    static int smem_set = 0;
    const int smem_bytes = 2 * V_ * (int)sizeof(float4);  // 160,736 B
    if (!smem_set) {
        cudaFuncSetAttribute(se3_frame_kernel,
                             cudaFuncAttributeMaxDynamicSharedMemorySize, smem_bytes);
        smem_set = 1;
    }

    detect_mask_kernel<<<1, 128>>>((const unsigned int*)mask);
    se3_frame_kernel<<<T_, THREADS, smem_bytes>>>(can, def, nbr, mask, out);
}

// round 3
// speedup vs baseline: 2.2756x; 1.0095x over previous
#include <cuda_runtime.h>
#include <cstdint>

#define T_ 128
#define V_ 5023
#define K_ 16
#define NTV (T_ * V_)
#define THREADS 768

// 0 = uint8 (numpy bool), 1 = int32, 2 = float32
__device__ int g_mask_mode;

__global__ void detect_mask_kernel(const unsigned int* __restrict__ w) {
    __shared__ int flags[3];
    if (threadIdx.x < 3) flags[threadIdx.x] = 0;
    __syncthreads();
    for (int i = threadIdx.x; i < 512; i += blockDim.x) {
        unsigned int x = w[i];
        if (x == 0u) continue;
        if (x == 1u) atomicOr(&flags[0], 1);
        else if (x == 0x3F800000u) atomicOr(&flags[1], 1);
        else atomicOr(&flags[2], 1);
    }
    __syncthreads();
    if (threadIdx.x == 0) {
        g_mask_mode = flags[2] ? 0 : (flags[1] ? 2 : 1);
    }
}

extern __shared__ float s_rec[];  // [6 * V_] : {can.xyz, def.xyz} per vertex

__global__ void __launch_bounds__(THREADS)
se3_frame_kernel(const float* __restrict__ can, const float* __restrict__ def,
                 const int* __restrict__ nbr, const void* __restrict__ maskp,
                 float* __restrict__ out) {
    const int t = blockIdx.x;
    const int tid = threadIdx.x;
    const float* canT = can + (size_t)t * (V_ * 3);
    const float* defT = def + (size_t)t * (V_ * 3);

    // ---- stage this frame's positions into smem as packed 24B records ----
    for (int v = tid; v < V_; v += THREADS) {
        int b = 3 * v;
        float* r = s_rec + 6 * v;
        r[0] = canT[b]; r[1] = canT[b + 1]; r[2] = canT[b + 2];
        r[3] = defT[b]; r[4] = defT[b + 1]; r[5] = defT[b + 2];
    }
    __syncthreads();

    const int mode = g_mask_mode;
    float* outt = out + (size_t)NTV * 4;

    for (int v = tid; v < V_; v += THREADS) {
        // ---- active-neighbor bitmask (dtype-robust) ----
        unsigned int amask = 0;
        if (mode == 0) {
            uint4 mw = *(const uint4*)((const unsigned char*)maskp + (size_t)v * K_);
            unsigned int ws[4] = {mw.x, mw.y, mw.z, mw.w};
#pragma unroll
            for (int i = 0; i < K_; i++)
                if ((ws[i >> 2] >> ((i & 3) * 8)) & 0xFF) amask |= (1u << i);
        } else if (mode == 1) {
            const int4* mi = (const int4*)((const int*)maskp + (size_t)v * K_);
#pragma unroll
            for (int c = 0; c < 4; c++) {
                int4 x = mi[c];
                if (x.x) amask |= 1u << (c * 4 + 0);
                if (x.y) amask |= 1u << (c * 4 + 1);
                if (x.z) amask |= 1u << (c * 4 + 2);
                if (x.w) amask |= 1u << (c * 4 + 3);
            }
        } else {
            const float4* mf = (const float4*)((const float*)maskp + (size_t)v * K_);
#pragma unroll
            for (int c = 0; c < 4; c++) {
                float4 x = mf[c];
                if (x.x != 0.0f) amask |= 1u << (c * 4 + 0);
                if (x.y != 0.0f) amask |= 1u << (c * 4 + 1);
                if (x.z != 0.0f) amask |= 1u << (c * 4 + 2);
                if (x.w != 0.0f) amask |= 1u << (c * 4 + 3);
            }
        }

        // ---- neighbor indices ----
        int nb[K_];
        const int4* ni = (const int4*)(nbr + (size_t)v * K_);
#pragma unroll
        for (int c = 0; c < 4; c++) {
            int4 x = ni[c];
            nb[c * 4 + 0] = x.x; nb[c * 4 + 1] = x.y;
            nb[c * 4 + 2] = x.z; nb[c * 4 + 3] = x.w;
        }

        const float* rv = s_rec + 6 * v;
        float cx = rv[0], cy = rv[1], cz = rv[2];
        float dx = rv[3], dy = rv[4], dz = rv[5];

        // ---- masked gather sums over ACTIVE neighbors only ----
        // G1 = sum P, G2 = sum Q, G3[i][j] = sum Q_i * P_j
        float G1x = 0, G1y = 0, G1z = 0;
        float G2x = 0, G2y = 0, G2z = 0;
        float G300 = 0, G301 = 0, G302 = 0;
        float G310 = 0, G311 = 0, G312 = 0;
        float G320 = 0, G321 = 0, G322 = 0;
#pragma unroll
        for (int k = 0; k < K_; k++) {
            if ((amask >> k) & 1u) {
                const float2* rj = (const float2*)(s_rec + 6 * nb[k]);
                float2 r0 = rj[0];  // can.x, can.y
                float2 r1 = rj[1];  // can.z, def.x
                float2 r2 = rj[2];  // def.y, def.z
                float px = r0.x, py = r0.y, pz = r1.x;
                float qx = r1.y, qy = r2.x, qz = r2.y;
                G1x += px; G1y += py; G1z += pz;
                G2x += qx; G2y += qy; G2z += qz;
                G300 = fmaf(qx, px, G300); G301 = fmaf(qx, py, G301); G302 = fmaf(qx, pz, G302);
                G310 = fmaf(qy, px, G310); G311 = fmaf(qy, py, G311); G312 = fmaf(qy, pz, G312);
                G320 = fmaf(qz, px, G320); G321 = fmaf(qz, py, G321); G322 = fmaf(qz, pz, G322);
            }
        }

        // A[i][j] = G3[i][j] - G2_i*c_j - d_i*(G1_j - 16*c_j)
        float Hx = fmaf(-16.0f, cx, G1x);
        float Hy = fmaf(-16.0f, cy, G1y);
        float Hz = fmaf(-16.0f, cz, G1z);
        float A00 = G300 - G2x * cx - dx * Hx;
        float A01 = G301 - G2x * cy - dx * Hy;
        float A02 = G302 - G2x * cz - dx * Hz;
        float A10 = G310 - G2y * cx - dy * Hx;
        float A11 = G311 - G2y * cy - dy * Hy;
        float A12 = G312 - G2y * cz - dy * Hz;
        float A20 = G320 - G2z * cx - dz * Hx;
        float A21 = G321 - G2z * cy - dz * Hy;
        float A22 = G322 - G2z * cz - dz * Hz;

        // ---- Davenport K matrix (symmetric, trace 0) ----
        float k00 = A00 + A11 + A22;
        float k11 = A00 - A11 - A22;
        float k22 = -A00 + A11 - A22;
        float k33 = -A00 - A11 + A22;
        float k01 = A21 - A12;
        float k02 = A02 - A20;
        float k03 = A10 - A01;
        float k12 = A01 + A10;
        float k13 = A02 + A20;
        float k23 = A12 + A21;

        // ---- characteristic quartic: f(x) = x^4 + c2 x^2 + c1 x + c0 ----
        float trAtA = A00 * A00 + A01 * A01 + A02 * A02 +
                      A10 * A10 + A11 * A11 + A12 * A12 +
                      A20 * A20 + A21 * A21 + A22 * A22;
        float c2 = -2.0f * trAtA;
        float detA = A00 * (A11 * A22 - A12 * A21)
                   - A01 * (A10 * A22 - A12 * A20)
                   + A02 * (A10 * A21 - A11 * A20);
        float c1 = -8.0f * detA;
        float M0 = k11 * (k22 * k33 - k23 * k23)
                 - k12 * (k12 * k33 - k23 * k13)
                 + k13 * (k12 * k23 - k22 * k13);
        float M1 = k01 * (k22 * k33 - k23 * k23)
                 - k12 * (k02 * k33 - k23 * k03)
                 + k13 * (k02 * k23 - k22 * k03);
        float M2 = k01 * (k12 * k33 - k23 * k13)
                 - k11 * (k02 * k33 - k23 * k03)
                 + k13 * (k02 * k13 - k12 * k03);
        float M3 = k01 * (k12 * k23 - k22 * k13)
                 - k11 * (k02 * k23 - k22 * k03)
                 + k12 * (k02 * k13 - k12 * k03);
        float c0 = k00 * M0 - k01 * M1 + k02 * M2 - k03 * M3;

        // ---- Newton from upper bound lam0 = sqrt(3 * tr(A^T A)) >= lam_max ----
        float lam = 1.7320508f * sqrtf(trAtA);
        float fp = 1.0f;
#pragma unroll
        for (int it = 0; it < 9; it++) {
            float lam2 = lam * lam;
            float f = (lam2 + c2) * lam2 + fmaf(c1, lam, c0);
            fp = fmaf(4.0f * lam2 + 2.0f * c2, lam, c1);
            lam -= __fdividef(f, fp);
        }

        // ---- eigenvector via -adj(B), B = K - lam*I ----
        float b00 = k00 - lam, b11 = k11 - lam, b22 = k22 - lam, b33 = k33 - lam;
        float a3 = 4.0f * lam;
        float a2 = fmaf(6.0f * lam, lam, c2);
        float a1 = fp;

        float C00 = b00 * b00 + k01 * k01 + k02 * k02 + k03 * k03;
        float C01 = b00 * k01 + k01 * b11 + k02 * k12 + k03 * k13;
        float C02 = b00 * k02 + k01 * k12 + k02 * b22 + k03 * k23;
        float C03 = b00 * k03 + k01 * k13 + k02 * k23 + k03 * b33;
        float C11 = k01 * k01 + b11 * b11 + k12 * k12 + k13 * k13;
        float C12 = k01 * k02 + b11 * k12 + k12 * b22 + k13 * k23;
        float C13 = k01 * k03 + b11 * k13 + k12 * k23 + k13 * b33;
        float C22 = k02 * k02 + k12 * k12 + b22 * b22 + k23 * k23;
        float C23 = k02 * k03 + k12 * k13 + b22 * k23 + k23 * b33;
        float C33 = k03 * k03 + k13 * k13 + k23 * k23 + b33 * b33;

        float P00 = b00 * C00 + k01 * C01 + k02 * C02 + k03 * C03;
        float P01 = b00 * C01 + k01 * C11 + k02 * C12 + k03 * C13;
        float P02 = b00 * C02 + k01 * C12 + k02 * C22 + k03 * C23;
        float P03 = b00 * C03 + k01 * C13 + k02 * C23 + k03 * C33;
        float P11 = k01 * C01 + b11 * C11 + k12 * C12 + k13 * C13;
        float P12 = k01 * C02 + b11 * C12 + k12 * C22 + k13 * C23;
        float P13 = k01 * C03 + b11 * C13 + k12 * C23 + k13 * C33;
        float P22 = k02 * C02 + k12 * C12 + b22 * C22 + k23 * C23;
        float P23 = k02 * C03 + k12 * C13 + b22 * C23 + k23 * C33;
        float P33 = k03 * C03 + k13 * C13 + k23 * C23 + b33 * C33;

        float M00 = P00 + a3 * C00 + a2 * b00 + a1;
        float M01 = P01 + a3 * C01 + a2 * k01;
        float M02 = P02 + a3 * C02 + a2 * k02;
        float M03 = P03 + a3 * C03 + a2 * k03;
        float M11 = P11 + a3 * C11 + a2 * b11 + a1;
        float M12 = P12 + a3 * C12 + a2 * k12;
        float M13 = P13 + a3 * C13 + a2 * k13;
        float M22 = P22 + a3 * C22 + a2 * b22 + a1;
        float M23 = P23 + a3 * C23 + a2 * k23;
        float M33 = P33 + a3 * C33 + a2 * b33 + a1;

        // pick the column with the largest |diagonal| (best-conditioned)
        float qw = M00, qx = M01, qy = M02, qz = M03;
        float bd = fabsf(M00);
        if (fabsf(M11) > bd) { bd = fabsf(M11); qw = M01; qx = M11; qy = M12; qz = M13; }
        if (fabsf(M22) > bd) { bd = fabsf(M22); qw = M02; qx = M12; qy = M22; qz = M23; }
        if (fabsf(M33) > bd) { bd = fabsf(M33); qw = M03; qx = M13; qy = M23; qz = M33; }

        // sign convention: component with largest |value| (w,x,y,z, first on ties) positive
        float aw = fabsf(qw), ax = fabsf(qx), ay = fabsf(qy), az = fabsf(qz);
        float besta = aw, piv = qw;
        if (ax > besta) { besta = ax; piv = qx; }
        if (ay > besta) { besta = ay; piv = qy; }
        if (az > besta) { besta = az; piv = qz; }
        float invn = rsqrtf(fmaf(qw, qw, fmaf(qx, qx, fmaf(qy, qy, qz * qz))));
        if (piv < 0.0f) invn = -invn;

        int idx = t * V_ + v;
        ((float4*)out)[idx] = make_float4(qw * invn, qx * invn, qy * invn, qz * invn);
        outt[idx * 3 + 0] = dx - cx;
        outt[idx * 3 + 1] = dy - cy;
        outt[idx * 3 + 2] = dz - cz;
    }
}

extern "C" void kernel_launch(void* const* d_in, const int* in_sizes, int n_in,
                              void* d_out, int out_size) {
    const float* can = (const float*)d_in[0];
    const float* def = (const float*)d_in[1];
    const int* nbr = (const int*)d_in[2];
    const void* mask = d_in[3];
    float* out = (float*)d_out;

    static int smem_set = 0;
    const int smem_bytes = 6 * V_ * (int)sizeof(float);  // 120,552 B
    if (!smem_set) {
        cudaFuncSetAttribute(se3_frame_kernel,
                             cudaFuncAttributeMaxDynamicSharedMemorySize, smem_bytes);
        smem_set = 1;
    }

    detect_mask_kernel<<<1, 128>>>((const unsigned int*)mask);
    se3_frame_kernel<<<T_, THREADS, smem_bytes>>>(can, def, nbr, mask, out);
}

// round 6
// speedup vs baseline: 2.5666x; 1.1279x over previous
#include <cuda_runtime.h>
#include <cstdint>

#define T_ 128
#define V_ 5023
#define K_ 16
#define NTV (T_ * V_)
#define THREADS 1024

extern __shared__ float s_rec[];  // [6 * V_] : {can.xyz, def.xyz} per vertex

__global__ void __launch_bounds__(THREADS)
se3_frame_kernel(const float* __restrict__ can, const float* __restrict__ def,
                 const int* __restrict__ nbr, const void* __restrict__ maskp,
                 float* __restrict__ out) {
    const int t = blockIdx.x;
    const int tid = threadIdx.x;
    const float* canT = can + (size_t)t * (V_ * 3);
    const float* defT = def + (size_t)t * (V_ * 3);

    __shared__ int s_mode;  // 0 = uint8 bool, 1 = int32, 2 = float32

    // ---- inline mask dtype detection (warp 0, first 32 words = 128 bool bytes) ----
    if (tid < 32) {
        unsigned int x = ((const unsigned int*)maskp)[tid];
        bool weird = (x != 0u) && (x != 1u) && (x != 0x3F800000u);
        bool isf32 = (x == 0x3F800000u);
        unsigned bp = __ballot_sync(0xffffffffu, weird);
        unsigned fp = __ballot_sync(0xffffffffu, isf32);
        if (tid == 0) s_mode = bp ? 0 : (fp ? 2 : 1);
    }

    // ---- stage this frame's positions into smem as packed 24B records ----
    for (int v = tid; v < V_; v += THREADS) {
        int b = 3 * v;
        float* r = s_rec + 6 * v;
        r[0] = canT[b]; r[1] = canT[b + 1]; r[2] = canT[b + 2];
        r[3] = defT[b]; r[4] = defT[b + 1]; r[5] = defT[b + 2];
    }
    __syncthreads();

    const int mode = s_mode;
    float* outt = out + (size_t)NTV * 4;

    for (int v = tid; v < V_; v += THREADS) {
        // ---- active-neighbor bitmask (dtype-robust) ----
        unsigned int amask = 0;
        if (mode == 0) {
            uint4 mw = *(const uint4*)((const unsigned char*)maskp + (size_t)v * K_);
            unsigned int ws[4] = {mw.x, mw.y, mw.z, mw.w};
#pragma unroll
            for (int i = 0; i < K_; i++)
                if ((ws[i >> 2] >> ((i & 3) * 8)) & 0xFF) amask |= (1u << i);
        } else if (mode == 1) {
            const int4* mi = (const int4*)((const int*)maskp + (size_t)v * K_);
#pragma unroll
            for (int c = 0; c < 4; c++) {
                int4 x = mi[c];
                if (x.x) amask |= 1u << (c * 4 + 0);
                if (x.y) amask |= 1u << (c * 4 + 1);
                if (x.z) amask |= 1u << (c * 4 + 2);
                if (x.w) amask |= 1u << (c * 4 + 3);
            }
        } else {
            const float4* mf = (const float4*)((const float*)maskp + (size_t)v * K_);
#pragma unroll
            for (int c = 0; c < 4; c++) {
                float4 x = mf[c];
                if (x.x != 0.0f) amask |= 1u << (c * 4 + 0);
                if (x.y != 0.0f) amask |= 1u << (c * 4 + 1);
                if (x.z != 0.0f) amask |= 1u << (c * 4 + 2);
                if (x.w != 0.0f) amask |= 1u << (c * 4 + 3);
            }
        }

        // ---- neighbor indices ----
        int nb[K_];
        const int4* ni = (const int4*)(nbr + (size_t)v * K_);
#pragma unroll
        for (int c = 0; c < 4; c++) {
            int4 x = ni[c];
            nb[c * 4 + 0] = x.x; nb[c * 4 + 1] = x.y;
            nb[c * 4 + 2] = x.z; nb[c * 4 + 3] = x.w;
        }

        const float* rv = s_rec + 6 * v;
        float cx = rv[0], cy = rv[1], cz = rv[2];
        float dx = rv[3], dy = rv[4], dz = rv[5];

        // ---- masked gather sums over ACTIVE neighbors only ----
        float G1x = 0, G1y = 0, G1z = 0;
        float G2x = 0, G2y = 0, G2z = 0;
        float G300 = 0, G301 = 0, G302 = 0;
        float G310 = 0, G311 = 0, G312 = 0;
        float G320 = 0, G321 = 0, G322 = 0;
        // batch-2 software pipeline for higher LDS MLP
#pragma unroll
        for (int k = 0; k < K_; k += 2) {
            bool a0 = (amask >> k) & 1u;
            bool a1_ = (amask >> (k + 1)) & 1u;
            float2 r0a, r1a, r2a, r0b, r1b, r2b;
            if (a0) {
                const float2* rj = (const float2*)(s_rec + 6 * nb[k]);
                r0a = rj[0]; r1a = rj[1]; r2a = rj[2];
            }
            if (a1_) {
                const float2* rj = (const float2*)(s_rec + 6 * nb[k + 1]);
                r0b = rj[0]; r1b = rj[1]; r2b = rj[2];
            }
            if (a0) {
                float px = r0a.x, py = r0a.y, pz = r1a.x;
                float qx = r1a.y, qy = r2a.x, qz = r2a.y;
                G1x += px; G1y += py; G1z += pz;
                G2x += qx; G2y += qy; G2z += qz;
                G300 = fmaf(qx, px, G300); G301 = fmaf(qx, py, G301); G302 = fmaf(qx, pz, G302);
                G310 = fmaf(qy, px, G310); G311 = fmaf(qy, py, G311); G312 = fmaf(qy, pz, G312);
                G320 = fmaf(qz, px, G320); G321 = fmaf(qz, py, G321); G322 = fmaf(qz, pz, G322);
            }
            if (a1_) {
                float px = r0b.x, py = r0b.y, pz = r1b.x;
                float qx = r1b.y, qy = r2b.x, qz = r2b.y;
                G1x += px; G1y += py; G1z += pz;
                G2x += qx; G2y += qy; G2z += qz;
                G300 = fmaf(qx, px, G300); G301 = fmaf(qx, py, G301); G302 = fmaf(qx, pz, G302);
                G310 = fmaf(qy, px, G310); G311 = fmaf(qy, py, G311); G312 = fmaf(qy, pz, G312);
                G320 = fmaf(qz, px, G320); G321 = fmaf(qz, py, G321); G322 = fmaf(qz, pz, G322);
            }
        }

        // A[i][j] = G3[i][j] - G2_i*c_j - d_i*(G1_j - 16*c_j)
        float Hx = fmaf(-16.0f, cx, G1x);
        float Hy = fmaf(-16.0f, cy, G1y);
        float Hz = fmaf(-16.0f, cz, G1z);
        float A00 = G300 - G2x * cx - dx * Hx;
        float A01 = G301 - G2x * cy - dx * Hy;
        float A02 = G302 - G2x * cz - dx * Hz;
        float A10 = G310 - G2y * cx - dy * Hx;
        float A11 = G311 - G2y * cy - dy * Hy;
        float A12 = G312 - G2y * cz - dy * Hz;
        float A20 = G320 - G2z * cx - dz * Hx;
        float A21 = G321 - G2z * cy - dz * Hy;
        float A22 = G322 - G2z * cz - dz * Hz;

        // ---- Davenport K matrix (symmetric, trace 0) ----
        float k00 = A00 + A11 + A22;
        float k11 = A00 - A11 - A22;
        float k22 = -A00 + A11 - A22;
        float k33 = -A00 - A11 + A22;
        float k01 = A21 - A12;
        float k02 = A02 - A20;
        float k03 = A10 - A01;
        float k12 = A01 + A10;
        float k13 = A02 + A20;
        float k23 = A12 + A21;

        // ---- characteristic quartic: f(x) = x^4 + c2 x^2 + c1 x + c0 ----
        float trAtA = A00 * A00 + A01 * A01 + A02 * A02 +
                      A10 * A10 + A11 * A11 + A12 * A12 +
                      A20 * A20 + A21 * A21 + A22 * A22;
        float c2 = -2.0f * trAtA;
        float detA = A00 * (A11 * A22 - A12 * A21)
                   - A01 * (A10 * A22 - A12 * A20)
                   + A02 * (A10 * A21 - A11 * A20);
        float c1 = -8.0f * detA;
        float M0 = k11 * (k22 * k33 - k23 * k23)
                 - k12 * (k12 * k33 - k23 * k13)
                 + k13 * (k12 * k23 - k22 * k13);
        float M1 = k01 * (k22 * k33 - k23 * k23)
                 - k12 * (k02 * k33 - k23 * k03)
                 + k13 * (k02 * k23 - k22 * k03);
        float M2 = k01 * (k12 * k33 - k23 * k13)
                 - k11 * (k02 * k33 - k23 * k03)
                 + k13 * (k02 * k13 - k12 * k03);
        float M3 = k01 * (k12 * k23 - k22 * k13)
                 - k11 * (k02 * k23 - k22 * k03)
                 + k12 * (k02 * k13 - k12 * k03);
        float c0 = k00 * M0 - k01 * M1 + k02 * M2 - k03 * M3;

        // ---- Newton from upper bound lam0 = sqrt(3 * tr(A^T A)) >= lam_max ----
        float lam = 1.7320508f * sqrtf(trAtA);
        float fp2 = 1.0f;
#pragma unroll
        for (int it = 0; it < 7; it++) {
            float lam2 = lam * lam;
            float f = (lam2 + c2) * lam2 + fmaf(c1, lam, c0);
            fp2 = fmaf(4.0f * lam2 + 2.0f * c2, lam, c1);
            lam -= __fdividef(f, fp2);
        }

        // ---- eigenvector: column 0 of M = B^3 + a3 B^2 + a2 B + a1 I ----
        float b00 = k00 - lam, b11 = k11 - lam, b22 = k22 - lam, b33 = k33 - lam;
        float a3 = 4.0f * lam;
        float a2 = fmaf(6.0f * lam, lam, c2);
        float a1 = fp2;

        // u1 = B e0 (first column of B)
        float u10 = b00, u11 = k01, u12 = k02, u13 = k03;
        // u2 = B u1
        float u20 = b00 * u10 + k01 * u11 + k02 * u12 + k03 * u13;
        float u21 = k01 * u10 + b11 * u11 + k12 * u12 + k13 * u13;
        float u22 = k02 * u10 + k12 * u11 + b22 * u12 + k23 * u13;
        float u23 = k03 * u10 + k13 * u11 + k23 * u12 + b33 * u13;
        // u3 = B u2
        float u30 = b00 * u20 + k01 * u21 + k02 * u22 + k03 * u23;
        float u31 = k01 * u20 + b11 * u21 + k12 * u22 + k13 * u23;
        float u32 = k02 * u20 + k12 * u21 + b22 * u22 + k23 * u23;
        float u33 = k03 * u20 + k13 * u21 + k23 * u22 + b33 * u23;

        float qw = u30 + a3 * u20 + a2 * u10 + a1;
        float qx = u31 + a3 * u21 + a2 * u11;
        float qy = u32 + a3 * u22 + a2 * u12;
        float qz = u33 + a3 * u23 + a2 * u13;

        float nq = fmaf(qw, qw, fmaf(qx, qx, fmaf(qy, qy, qz * qz)));
        if (nq < 1e-4f * a1 * a1) {
            // rare fallback (near-180-degree rotation): full adjugate, best column
            float C00 = b00 * b00 + k01 * k01 + k02 * k02 + k03 * k03;
            float C01 = b00 * k01 + k01 * b11 + k02 * k12 + k03 * k13;
            float C02 = b00 * k02 + k01 * k12 + k02 * b22 + k03 * k23;
            float C03 = b00 * k03 + k01 * k13 + k02 * k23 + k03 * b33;
            float C11 = k01 * k01 + b11 * b11 + k12 * k12 + k13 * k13;
            float C12 = k01 * k02 + b11 * k12 + k12 * b22 + k13 * k23;
            float C13 = k01 * k03 + b11 * k13 + k12 * k23 + k13 * b33;
            float C22 = k02 * k02 + k12 * k12 + b22 * b22 + k23 * k23;
            float C23 = k02 * k03 + k12 * k13 + b22 * k23 + k23 * b33;
            float C33 = k03 * k03 + k13 * k13 + k23 * k23 + b33 * b33;
            float P11v = k01 * C01 + b11 * C11 + k12 * C12 + k13 * C13;
            float P12v = k01 * C02 + b11 * C12 + k12 * C22 + k13 * C23;
            float P13v = k01 * C03 + b11 * C13 + k12 * C23 + k13 * C33;
            float P22v = k02 * C02 + k12 * C12 + b22 * C22 + k23 * C23;
            float P23v = k02 * C03 + k12 * C13 + b22 * C23 + k23 * C33;
            float P33v = k03 * C03 + k13 * C13 + k23 * C23 + b33 * C33;
            float P01v = b00 * C01 + k01 * C11 + k02 * C12 + k03 * C13;
            float P02v = b00 * C02 + k01 * C12 + k02 * C22 + k03 * C23;
            float P03v = b00 * C03 + k01 * C13 + k02 * C23 + k03 * C33;
            float N11 = P11v + a3 * C11 + a2 * b11 + a1;
            float N12 = P12v + a3 * C12 + a2 * k12;
            float N13 = P13v + a3 * C13 + a2 * k13;
            float N22 = P22v + a3 * C22 + a2 * b22 + a1;
            float N23 = P23v + a3 * C23 + a2 * k23;
            float N33 = P33v + a3 * C33 + a2 * b33 + a1;
            float N01 = P01v + a3 * C01 + a2 * k01;
            float N02 = P02v + a3 * C02 + a2 * k02;
            float N03 = P03v + a3 * C03 + a2 * k03;
            float bd = nq > 0 ? sqrtf(nq) : 0.0f;  // |col0|
            // pick column with largest diagonal magnitude among 1..3
            if (fabsf(N11) * 1.0f > bd) { bd = fabsf(N11); qw = N01; qx = N11; qy = N12; qz = N13; }
            if (fabsf(N22) > bd) { bd = fabsf(N22); qw = N02; qx = N12; qy = N22; qz = N23; }
            if (fabsf(N33) > bd) { qw = N03; qx = N13; qy = N23; qz = N33; }
        }

        // sign convention: component with largest |value| (w,x,y,z, first on ties) positive
        float aw = fabsf(qw), ax = fabsf(qx), ay = fabsf(qy), az = fabsf(qz);
        float besta = aw, piv = qw;
        if (ax > besta) { besta = ax; piv = qx; }
        if (ay > besta) { besta = ay; piv = qy; }
        if (az > besta) { besta = az; piv = qz; }
        float invn = rsqrtf(fmaf(qw, qw, fmaf(qx, qx, fmaf(qy, qy, qz * qz))));
        if (piv < 0.0f) invn = -invn;

        int idx = t * V_ + v;
        ((float4*)out)[idx] = make_float4(qw * invn, qx * invn, qy * invn, qz * invn);
        outt[idx * 3 + 0] = dx - cx;
        outt[idx * 3 + 1] = dy - cy;
        outt[idx * 3 + 2] = dz - cz;
    }
}

extern "C" void kernel_launch(void* const* d_in, const int* in_sizes, int n_in,
                              void* d_out, int out_size) {
    const float* can = (const float*)d_in[0];
    const float* def = (const float*)d_in[1];
    const int* nbr = (const int*)d_in[2];
    const void* mask = d_in[3];
    float* out = (float*)d_out;

    static int smem_set = 0;
    const int smem_bytes = 6 * V_ * (int)sizeof(float);  // 120,552 B
    if (!smem_set) {
        cudaFuncSetAttribute(se3_frame_kernel,
                             cudaFuncAttributeMaxDynamicSharedMemorySize, smem_bytes);
        smem_set = 1;
    }

    se3_frame_kernel<<<T_, THREADS, smem_bytes>>>(can, def, nbr, mask, out);
}